// round 4
// baseline (speedup 1.0000x reference)
#include <cuda_runtime.h>
#include <cstdint>

#define FF 128
#define HH 512
#define MAXN 50048

// Scratch (static device globals — no runtime allocation allowed)
__device__ float g_h[(size_t)50000 * HH];    // h' = (x @ W^T) * dinv[row]
__device__ float g_acc[(size_t)50000 * HH];  // scatter accumulator (atomics target)
__device__ float g_deg[MAXN];
__device__ float g_dinv[MAXN];

// ---------------------------------------------------------------------------
// Degree / normalization
// ---------------------------------------------------------------------------
__global__ void deg_init_kernel(int n) {
    int i = blockIdx.x * blockDim.x + threadIdx.x;
    if (i < n) g_deg[i] = 1.0f;  // self-loop contributes 1 to every node
}

__global__ void deg_edge_kernel(const int* __restrict__ ei, int E, int n) {
    int e = blockIdx.x * blockDim.x + threadIdx.x;
    if (e < E) {
        int c = ei[E + e];  // target column (int32 per harness dtype table)
        if (c >= 0 && c < n) atomicAdd(&g_deg[c], 1.0f);
    }
}

__global__ void dinv_kernel(int n) {
    int i = blockIdx.x * blockDim.x + threadIdx.x;
    if (i < n) g_dinv[i] = rsqrtf(g_deg[i]);
}

// ---------------------------------------------------------------------------
// SGEMM: h'[m][n] = dinv[m] * sum_k X[m][k] * W[n][k]
// Epilogue writes h' to g_h and initializes g_acc with the self-loop term.
// ---------------------------------------------------------------------------
__global__ void sgemm_scaled_kernel(const float* __restrict__ X,
                                    const float* __restrict__ W,
                                    int M) {
    constexpr int BM = 64, BN = 64, BK = 32, LD = BM + 4;  // LD=68 keeps 16B align
    __shared__ __align__(16) float Xs[BK][LD];
    __shared__ __align__(16) float Ws[BK][LD];

    const int t = threadIdx.x;
    const int bm = blockIdx.y * BM;
    const int bn = blockIdx.x * BN;
    const int ty = t >> 4;          // 0..15
    const int tx = t & 15;          // 0..15

    float acc[4][4] = {};

    for (int kt = 0; kt < FF; kt += BK) {
#pragma unroll
        for (int i = 0; i < 2; i++) {
            int idx = t + i * 256;          // 0..511
            int m   = idx >> 3;             // 0..63
            int k4  = idx & 7;              // 0..7
            int gm  = bm + m;
            float4 v = make_float4(0.f, 0.f, 0.f, 0.f);
            if (gm < M)
                v = *(const float4*)&X[(size_t)gm * FF + kt + k4 * 4];
            Xs[k4 * 4 + 0][m] = v.x;
            Xs[k4 * 4 + 1][m] = v.y;
            Xs[k4 * 4 + 2][m] = v.z;
            Xs[k4 * 4 + 3][m] = v.w;
        }
#pragma unroll
        for (int i = 0; i < 2; i++) {
            int idx = t + i * 256;
            int n   = idx >> 3;
            int k4  = idx & 7;
            float4 v = *(const float4*)&W[(size_t)(bn + n) * FF + kt + k4 * 4];
            Ws[k4 * 4 + 0][n] = v.x;
            Ws[k4 * 4 + 1][n] = v.y;
            Ws[k4 * 4 + 2][n] = v.z;
            Ws[k4 * 4 + 3][n] = v.w;
        }
        __syncthreads();

#pragma unroll
        for (int k = 0; k < BK; k++) {
            float4 a4 = *(const float4*)&Xs[k][ty * 4];
            float4 b4 = *(const float4*)&Ws[k][tx * 4];
            float av[4] = {a4.x, a4.y, a4.z, a4.w};
            float bv[4] = {b4.x, b4.y, b4.z, b4.w};
#pragma unroll
            for (int i = 0; i < 4; i++)
#pragma unroll
                for (int j = 0; j < 4; j++)
                    acc[i][j] += av[i] * bv[j];
        }
        __syncthreads();
    }

#pragma unroll
    for (int i = 0; i < 4; i++) {
        int gm = bm + ty * 4 + i;
        if (gm < M) {
            float s = g_dinv[gm];
            float4 v = make_float4(acc[i][0] * s, acc[i][1] * s,
                                   acc[i][2] * s, acc[i][3] * s);
            size_t off = (size_t)gm * HH + bn + tx * 4;
            *(float4*)&g_h[off] = v;
            *(float4*)&g_acc[off] = v;   // self-loop init of accumulator
        }
    }
}

// ---------------------------------------------------------------------------
// Edge scatter: g_acc[c] += h'[r]  (one warp per edge; 512 floats/row)
// ---------------------------------------------------------------------------
__global__ void scatter_edges_kernel(const int* __restrict__ ei, int E, int n) {
    int warp = (blockIdx.x * blockDim.x + threadIdx.x) >> 5;
    int lane = threadIdx.x & 31;
    if (warp >= E) return;
    int r = ei[warp];
    int c = ei[E + warp];
    if ((unsigned)r >= (unsigned)n || (unsigned)c >= (unsigned)n) return;
    const float4* src = (const float4*)&g_h[(size_t)r * HH];
    float*        dst = &g_acc[(size_t)c * HH];
#pragma unroll
    for (int i = 0; i < 4; i++) {
        int idx = lane + i * 32;           // float4 index 0..127
        float4 v = src[idx];
        float* d = dst + idx * 4;
        atomicAdd(d + 0, v.x);
        atomicAdd(d + 1, v.y);
        atomicAdd(d + 2, v.z);
        atomicAdd(d + 3, v.w);
    }
}

// ---------------------------------------------------------------------------
// Finalize: out = prelu(dinv[node] * g_acc + b, alpha)  (plain stores to d_out)
// ---------------------------------------------------------------------------
__global__ void finalize_kernel(float* __restrict__ out,
                                const float* __restrict__ b,
                                const float* __restrict__ alpha,
                                int n) {
    int tid = blockIdx.x * blockDim.x + threadIdx.x;
    int total = n * (HH / 4);
    if (tid >= total) return;
    int node = tid >> 7;         // /128 (HH/4 = 128)
    int c4   = tid & 127;
    float s = g_dinv[node];
    size_t off = (size_t)node * HH + c4 * 4;
    float4 v  = *(const float4*)&g_acc[off];
    float4 bb = *(const float4*)&b[c4 * 4];
    float4 aa = *(const float4*)&alpha[c4 * 4];
    v.x = v.x * s + bb.x;  v.x = v.x > 0.f ? v.x : aa.x * v.x;
    v.y = v.y * s + bb.y;  v.y = v.y > 0.f ? v.y : aa.y * v.y;
    v.z = v.z * s + bb.z;  v.z = v.z > 0.f ? v.z : aa.z * v.z;
    v.w = v.w * s + bb.w;  v.w = v.w > 0.f ? v.w : aa.w * v.w;
    *(float4*)&out[off] = v;
}

// ---------------------------------------------------------------------------
// Launch
// ---------------------------------------------------------------------------
extern "C" void kernel_launch(void* const* d_in, const int* in_sizes, int n_in,
                              void* d_out, int out_size) {
    const float* x     = (const float*)d_in[0];  // [N, 128]
    const int*   ei    = (const int*)d_in[1];    // [2, E] int32 (harness dtype table)
    const float* W     = (const float*)d_in[2];  // [512, 128]
    const float* b     = (const float*)d_in[3];  // [512]
    const float* alpha = (const float*)d_in[4];  // [512]
    float*       out   = (float*)d_out;          // [N, 512]

    const int N = in_sizes[0] / FF;
    const int E = in_sizes[1] / 2;

    // 1) degrees (self-loop + edge targets) -> dinv
    deg_init_kernel<<<(N + 255) / 256, 256>>>(N);
    deg_edge_kernel<<<(E + 255) / 256, 256>>>(ei, E, N);
    dinv_kernel<<<(N + 255) / 256, 256>>>(N);

    // 2) h' = (x @ W^T) * dinv[row]; also initializes g_acc with self-loop term
    dim3 gemm_grid(HH / 64, (N + 63) / 64);
    sgemm_scaled_kernel<<<gemm_grid, 256>>>(x, W, N);

    // 3) edge scatter-add into g_acc (warp per edge)
    int warps_per_block = 256 / 32;
    scatter_edges_kernel<<<(E + warps_per_block - 1) / warps_per_block, 256>>>(ei, E, N);

    // 4) out = prelu(dinv * g_acc + b)
    finalize_kernel<<<(N * (HH / 4) + 255) / 256, 256>>>(out, b, alpha, N);
}

// round 5
// speedup vs baseline: 2.4189x; 2.4189x over previous
#include <cuda_runtime.h>
#include <cstdint>

#define FF 128
#define HH 512
#define MAXN 50048
#define MAXE 401408
#define SCAN_B 1024

// Scratch (static device globals — no runtime allocation allowed)
__device__ float g_h[(size_t)50000 * HH];   // h' = (x @ W^T) * dinv[row]
__device__ int   g_cnt[MAXN];               // in-degree (by target), excl. self-loop
__device__ float g_dinv[MAXN];
__device__ int   g_rowptr[MAXN + 1];
__device__ int   g_cur[MAXN];
__device__ int   g_srcidx[MAXE];
__device__ int   g_bsum[256];
__device__ int   g_boff[256];

// ---------------------------------------------------------------------------
// CSR build: count -> scan -> fill
// ---------------------------------------------------------------------------
__global__ void zero_cnt_kernel(int n) {
    int i = blockIdx.x * blockDim.x + threadIdx.x;
    if (i < n) g_cnt[i] = 0;
}

__global__ void count_kernel(const int* __restrict__ ei, int E, int n) {
    int e = blockIdx.x * blockDim.x + threadIdx.x;
    if (e < E) {
        int c = ei[E + e];
        if ((unsigned)c < (unsigned)n) atomicAdd(&g_cnt[c], 1);
    }
}

__global__ void dinv_kernel(int n) {
    int i = blockIdx.x * blockDim.x + threadIdx.x;
    if (i < n) g_dinv[i] = rsqrtf((float)(g_cnt[i] + 1));  // +1 self-loop
}

// Per-block exclusive scan (Hillis-Steele), emits block totals
__global__ void scan_block_kernel(int n) {
    __shared__ int sh[SCAN_B];
    int gid = blockIdx.x * SCAN_B + threadIdx.x;
    int v = (gid < n) ? g_cnt[gid] : 0;
    sh[threadIdx.x] = v;
    __syncthreads();
#pragma unroll
    for (int off = 1; off < SCAN_B; off <<= 1) {
        int t = (threadIdx.x >= off) ? sh[threadIdx.x - off] : 0;
        __syncthreads();
        sh[threadIdx.x] += t;
        __syncthreads();
    }
    if (gid < n) g_rowptr[gid] = sh[threadIdx.x] - v;   // exclusive
    if (threadIdx.x == SCAN_B - 1) g_bsum[blockIdx.x] = sh[threadIdx.x];
}

__global__ void scan_sums_kernel(int nb) {
    __shared__ int sh[256];
    int v = (threadIdx.x < nb) ? g_bsum[threadIdx.x] : 0;
    sh[threadIdx.x] = v;
    __syncthreads();
#pragma unroll
    for (int off = 1; off < 256; off <<= 1) {
        int t = (threadIdx.x >= off) ? sh[threadIdx.x - off] : 0;
        __syncthreads();
        sh[threadIdx.x] += t;
        __syncthreads();
    }
    if (threadIdx.x < nb) g_boff[threadIdx.x] = sh[threadIdx.x] - v;  // exclusive
}

__global__ void add_off_kernel(int n, int E) {
    int i = blockIdx.x * blockDim.x + threadIdx.x;
    if (i < n) {
        int v = g_rowptr[i] + g_boff[i / SCAN_B];
        g_rowptr[i] = v;
        g_cur[i] = v;
    }
    if (i == 0) g_rowptr[n] = E;
}

__global__ void fill_kernel(const int* __restrict__ ei, int E, int n) {
    int e = blockIdx.x * blockDim.x + threadIdx.x;
    if (e < E) {
        int r = ei[e];
        int c = ei[E + e];
        if ((unsigned)r < (unsigned)n && (unsigned)c < (unsigned)n) {
            int pos = atomicAdd(&g_cur[c], 1);
            g_srcidx[pos] = r;
        }
    }
}

// ---------------------------------------------------------------------------
// SGEMM: g_h[m][n] = dinv[m] * sum_k X[m][k] * W[n][k]
// ---------------------------------------------------------------------------
__global__ void sgemm_scaled_kernel(const float* __restrict__ X,
                                    const float* __restrict__ W,
                                    int M) {
    constexpr int BM = 64, BN = 64, BK = 32, LD = BM + 4;
    __shared__ __align__(16) float Xs[BK][LD];
    __shared__ __align__(16) float Ws[BK][LD];

    const int t = threadIdx.x;
    const int bm = blockIdx.y * BM;
    const int bn = blockIdx.x * BN;
    const int ty = t >> 4;
    const int tx = t & 15;

    float acc[4][4] = {};

    for (int kt = 0; kt < FF; kt += BK) {
#pragma unroll
        for (int i = 0; i < 2; i++) {
            int idx = t + i * 256;
            int m   = idx >> 3;
            int k4  = idx & 7;
            int gm  = bm + m;
            float4 v = make_float4(0.f, 0.f, 0.f, 0.f);
            if (gm < M)
                v = *(const float4*)&X[(size_t)gm * FF + kt + k4 * 4];
            Xs[k4 * 4 + 0][m] = v.x;
            Xs[k4 * 4 + 1][m] = v.y;
            Xs[k4 * 4 + 2][m] = v.z;
            Xs[k4 * 4 + 3][m] = v.w;
        }
#pragma unroll
        for (int i = 0; i < 2; i++) {
            int idx = t + i * 256;
            int nn  = idx >> 3;
            int k4  = idx & 7;
            float4 v = *(const float4*)&W[(size_t)(bn + nn) * FF + kt + k4 * 4];
            Ws[k4 * 4 + 0][nn] = v.x;
            Ws[k4 * 4 + 1][nn] = v.y;
            Ws[k4 * 4 + 2][nn] = v.z;
            Ws[k4 * 4 + 3][nn] = v.w;
        }
        __syncthreads();

#pragma unroll
        for (int k = 0; k < BK; k++) {
            float4 a4 = *(const float4*)&Xs[k][ty * 4];
            float4 b4 = *(const float4*)&Ws[k][tx * 4];
            float av[4] = {a4.x, a4.y, a4.z, a4.w};
            float bv[4] = {b4.x, b4.y, b4.z, b4.w};
#pragma unroll
            for (int i = 0; i < 4; i++)
#pragma unroll
                for (int j = 0; j < 4; j++)
                    acc[i][j] += av[i] * bv[j];
        }
        __syncthreads();
    }

#pragma unroll
    for (int i = 0; i < 4; i++) {
        int gm = bm + ty * 4 + i;
        if (gm < M) {
            float s = g_dinv[gm];
            float4 v = make_float4(acc[i][0] * s, acc[i][1] * s,
                                   acc[i][2] * s, acc[i][3] * s);
            *(float4*)&g_h[(size_t)gm * HH + bn + tx * 4] = v;
        }
    }
}

// ---------------------------------------------------------------------------
// Pull + finalize fused: one warp per node.
// out[v] = prelu(dinv[v] * (g_h[v] + sum_{u->v} g_h[u]) + b, alpha)
// Register accumulation — no atomics, single pass over output.
// ---------------------------------------------------------------------------
__global__ void pull_kernel(float* __restrict__ out,
                            const float* __restrict__ b,
                            const float* __restrict__ alpha,
                            int n) {
    int warp = (blockIdx.x * blockDim.x + threadIdx.x) >> 5;
    int lane = threadIdx.x & 31;
    if (warp >= n) return;
    int node = warp;
    int beg = g_rowptr[node];
    int end = g_rowptr[node + 1];

    const float4* self = (const float4*)&g_h[(size_t)node * HH];
    float4 acc[4];
#pragma unroll
    for (int i = 0; i < 4; i++) acc[i] = self[lane + i * 32];

    for (int e = beg; e < end; e++) {
        int r = g_srcidx[e];
        const float4* src = (const float4*)&g_h[(size_t)r * HH];
#pragma unroll
        for (int i = 0; i < 4; i++) {
            float4 v = src[lane + i * 32];
            acc[i].x += v.x; acc[i].y += v.y; acc[i].z += v.z; acc[i].w += v.w;
        }
    }

    float s = g_dinv[node];
    float* dst = &out[(size_t)node * HH];
#pragma unroll
    for (int i = 0; i < 4; i++) {
        int c4 = lane + i * 32;
        float4 bb = *(const float4*)&b[c4 * 4];
        float4 aa = *(const float4*)&alpha[c4 * 4];
        float4 v = acc[i];
        v.x = v.x * s + bb.x;  v.x = v.x > 0.f ? v.x : aa.x * v.x;
        v.y = v.y * s + bb.y;  v.y = v.y > 0.f ? v.y : aa.y * v.y;
        v.z = v.z * s + bb.z;  v.z = v.z > 0.f ? v.z : aa.z * v.z;
        v.w = v.w * s + bb.w;  v.w = v.w > 0.f ? v.w : aa.w * v.w;
        *(float4*)&dst[c4 * 4] = v;
    }
}

// ---------------------------------------------------------------------------
// Launch
// ---------------------------------------------------------------------------
extern "C" void kernel_launch(void* const* d_in, const int* in_sizes, int n_in,
                              void* d_out, int out_size) {
    const float* x     = (const float*)d_in[0];  // [N, 128]
    const int*   ei    = (const int*)d_in[1];    // [2, E] int32
    const float* W     = (const float*)d_in[2];  // [512, 128]
    const float* b     = (const float*)d_in[3];  // [512]
    const float* alpha = (const float*)d_in[4];  // [512]
    float*       out   = (float*)d_out;          // [N, 512]

    const int N = in_sizes[0] / FF;
    const int E = in_sizes[1] / 2;
    const int nb = (N + SCAN_B - 1) / SCAN_B;

    // 1) CSR build (by target) + dinv
    zero_cnt_kernel<<<(N + 255) / 256, 256>>>(N);
    count_kernel<<<(E + 255) / 256, 256>>>(ei, E, N);
    dinv_kernel<<<(N + 255) / 256, 256>>>(N);
    scan_block_kernel<<<nb, SCAN_B>>>(N);
    scan_sums_kernel<<<1, 256>>>(nb);
    add_off_kernel<<<(N + 255) / 256, 256>>>(N, E);
    fill_kernel<<<(E + 255) / 256, 256>>>(ei, E, N);

    // 2) g_h = (x @ W^T) * dinv[row]
    dim3 gemm_grid(HH / 64, (N + 63) / 64);
    sgemm_scaled_kernel<<<gemm_grid, 256>>>(x, W, N);

    // 3) pull-based aggregate + finalize (warp per node)
    int warps_per_block = 256 / 32;
    pull_kernel<<<(N + warps_per_block - 1) / warps_per_block, 256>>>(out, b, alpha, N);
}

// round 6
// speedup vs baseline: 3.4440x; 1.4238x over previous
#include <cuda_runtime.h>
#include <cstdint>

#define FF 128
#define HH 512
#define MAXN 50048
#define MAXE 401408
#define SCAN_B 1024

// Scratch (static device globals — no runtime allocation allowed)
__device__ float g_h[(size_t)50000 * HH];   // h' = (x @ W^T) * dinv[row]
__device__ int   g_cnt[MAXN];               // in-degree (by target), excl. self-loop
__device__ float g_dinv[MAXN];
__device__ int   g_rowptr[MAXN + 1];
__device__ int   g_cur[MAXN];
__device__ int   g_srcidx[MAXE];
__device__ int   g_bsum[256];
__device__ int   g_boff[256];

// ---------------------------------------------------------------------------
// CSR build: count -> scan -> fill
// ---------------------------------------------------------------------------
__global__ void zero_cnt_kernel(int n) {
    int i = blockIdx.x * blockDim.x + threadIdx.x;
    if (i < n) g_cnt[i] = 0;
}

__global__ void count_kernel(const int* __restrict__ ei, int E, int n) {
    int e = blockIdx.x * blockDim.x + threadIdx.x;
    if (e < E) {
        int c = ei[E + e];
        if ((unsigned)c < (unsigned)n) atomicAdd(&g_cnt[c], 1);
    }
}

__global__ void dinv_kernel(int n) {
    int i = blockIdx.x * blockDim.x + threadIdx.x;
    if (i < n) g_dinv[i] = rsqrtf((float)(g_cnt[i] + 1));  // +1 self-loop
}

// Per-block inclusive scan (Hillis-Steele) -> exclusive out, emits block totals
__global__ void scan_block_kernel(int n) {
    __shared__ int sh[SCAN_B];
    int gid = blockIdx.x * SCAN_B + threadIdx.x;
    int v = (gid < n) ? g_cnt[gid] : 0;
    sh[threadIdx.x] = v;
    __syncthreads();
#pragma unroll
    for (int off = 1; off < SCAN_B; off <<= 1) {
        int t = (threadIdx.x >= off) ? sh[threadIdx.x - off] : 0;
        __syncthreads();
        sh[threadIdx.x] += t;
        __syncthreads();
    }
    if (gid < n) g_rowptr[gid] = sh[threadIdx.x] - v;   // exclusive
    if (threadIdx.x == SCAN_B - 1) g_bsum[blockIdx.x] = sh[threadIdx.x];
}

__global__ void scan_sums_kernel(int nb) {
    __shared__ int sh[256];
    int v = (threadIdx.x < nb) ? g_bsum[threadIdx.x] : 0;
    sh[threadIdx.x] = v;
    __syncthreads();
#pragma unroll
    for (int off = 1; off < 256; off <<= 1) {
        int t = (threadIdx.x >= off) ? sh[threadIdx.x - off] : 0;
        __syncthreads();
        sh[threadIdx.x] += t;
        __syncthreads();
    }
    if (threadIdx.x < nb) g_boff[threadIdx.x] = sh[threadIdx.x] - v;  // exclusive
}

__global__ void add_off_kernel(int n, int E) {
    int i = blockIdx.x * blockDim.x + threadIdx.x;
    if (i < n) {
        int v = g_rowptr[i] + g_boff[i / SCAN_B];
        g_rowptr[i] = v;
        g_cur[i] = v;
    }
    if (i == 0) g_rowptr[n] = E;
}

__global__ void fill_kernel(const int* __restrict__ ei, int E, int n) {
    int e = blockIdx.x * blockDim.x + threadIdx.x;
    if (e < E) {
        int r = ei[e];
        int c = ei[E + e];
        if ((unsigned)r < (unsigned)n && (unsigned)c < (unsigned)n) {
            int pos = atomicAdd(&g_cur[c], 1);
            g_srcidx[pos] = r;
        }
    }
}

// ---------------------------------------------------------------------------
// tf32 tensor-core GEMM: g_h[m][n] = dinv[m] * sum_k X[m][k] * W[n][k]
// BM=128, BN=128, BK=32, 256 threads (8 warps, warp tile 32x64),
// mma.sync.m16n8k8.tf32. Conflict-free fragment LDS via LD=36 padding.
// ---------------------------------------------------------------------------
__device__ __forceinline__ uint32_t f2tf(float x) {
    uint32_t u;
    asm("cvt.rna.tf32.f32 %0, %1;" : "=r"(u) : "f"(x));
    return u;
}

__device__ __forceinline__ void mma8(float* c, const uint32_t* a,
                                     uint32_t b0, uint32_t b1) {
    asm volatile(
        "mma.sync.aligned.m16n8k8.row.col.f32.tf32.tf32.f32 "
        "{%0,%1,%2,%3}, {%4,%5,%6,%7}, {%8,%9}, {%0,%1,%2,%3};"
        : "+f"(c[0]), "+f"(c[1]), "+f"(c[2]), "+f"(c[3])
        : "r"(a[0]), "r"(a[1]), "r"(a[2]), "r"(a[3]), "r"(b0), "r"(b1));
}

__global__ __launch_bounds__(256) void tf32_gemm_kernel(
        const float* __restrict__ X, const float* __restrict__ W, int M) {
    constexpr int BM = 128, BN = 128, BK = 32, LD = BK + 4;  // LD=36
    __shared__ uint32_t As[BM][LD];
    __shared__ uint32_t Bs[BN][LD];

    const int t    = threadIdx.x;
    const int wid  = t >> 5;
    const int lane = t & 31;
    const int warp_m = wid & 3;   // 4 warps along M (32 rows each)
    const int warp_n = wid >> 2;  // 2 warps along N (64 cols each)
    const int bm = blockIdx.y * BM;
    const int bn = blockIdx.x * BN;

    float c[2][8][4];
#pragma unroll
    for (int mt = 0; mt < 2; mt++)
#pragma unroll
        for (int nt = 0; nt < 8; nt++)
#pragma unroll
            for (int q = 0; q < 4; q++) c[mt][nt][q] = 0.f;

    for (int kt = 0; kt < FF; kt += BK) {
        // A tile: 128 x 32 floats = 1024 float4; 4 per thread
#pragma unroll
        for (int i = 0; i < 4; i++) {
            int idx = t + i * 256;
            int row = idx >> 3, c4 = idx & 7;
            int gm = bm + row;
            float4 v = make_float4(0.f, 0.f, 0.f, 0.f);
            if (gm < M) v = *(const float4*)&X[(size_t)gm * FF + kt + c4 * 4];
            uint32_t* s = &As[row][c4 * 4];
            s[0] = f2tf(v.x); s[1] = f2tf(v.y); s[2] = f2tf(v.z); s[3] = f2tf(v.w);
        }
        // B tile: W rows bn..bn+127 (always < 512, no guard)
#pragma unroll
        for (int i = 0; i < 4; i++) {
            int idx = t + i * 256;
            int row = idx >> 3, c4 = idx & 7;
            float4 v = *(const float4*)&W[(size_t)(bn + row) * FF + kt + c4 * 4];
            uint32_t* s = &Bs[row][c4 * 4];
            s[0] = f2tf(v.x); s[1] = f2tf(v.y); s[2] = f2tf(v.z); s[3] = f2tf(v.w);
        }
        __syncthreads();

#pragma unroll
        for (int ks = 0; ks < 4; ks++) {
            const int k0 = ks * 8;
            const int kc = k0 + (lane & 3);
            uint32_t a[2][4];
#pragma unroll
            for (int mt = 0; mt < 2; mt++) {
                int r = warp_m * 32 + mt * 16 + (lane >> 2);
                a[mt][0] = As[r][kc];
                a[mt][1] = As[r + 8][kc];
                a[mt][2] = As[r][kc + 4];
                a[mt][3] = As[r + 8][kc + 4];
            }
#pragma unroll
            for (int nt = 0; nt < 8; nt++) {
                int nr = warp_n * 64 + nt * 8 + (lane >> 2);
                uint32_t b0 = Bs[nr][kc];
                uint32_t b1 = Bs[nr][kc + 4];
#pragma unroll
                for (int mt = 0; mt < 2; mt++)
                    mma8(c[mt][nt], a[mt], b0, b1);
            }
        }
        __syncthreads();
    }

    // Epilogue: scale by dinv[row], float2 stores (c0,c1 / c2,c3 are adjacent)
#pragma unroll
    for (int mt = 0; mt < 2; mt++) {
        int r0 = bm + warp_m * 32 + mt * 16 + (lane >> 2);
        int r1 = r0 + 8;
        float s0 = (r0 < M) ? g_dinv[r0] : 0.f;
        float s1 = (r1 < M) ? g_dinv[r1] : 0.f;
#pragma unroll
        for (int nt = 0; nt < 8; nt++) {
            int col = bn + warp_n * 64 + nt * 8 + (lane & 3) * 2;
            if (r0 < M) {
                float2 v = make_float2(c[mt][nt][0] * s0, c[mt][nt][1] * s0);
                *(float2*)&g_h[(size_t)r0 * HH + col] = v;
            }
            if (r1 < M) {
                float2 v = make_float2(c[mt][nt][2] * s1, c[mt][nt][3] * s1);
                *(float2*)&g_h[(size_t)r1 * HH + col] = v;
            }
        }
    }
}

// ---------------------------------------------------------------------------
// Pull + finalize fused: one warp per node.
// out[v] = prelu(dinv[v] * (g_h[v] + sum_{u->v} g_h[u]) + b, alpha)
// ---------------------------------------------------------------------------
__global__ void pull_kernel(float* __restrict__ out,
                            const float* __restrict__ b,
                            const float* __restrict__ alpha,
                            int n) {
    int warp = (blockIdx.x * blockDim.x + threadIdx.x) >> 5;
    int lane = threadIdx.x & 31;
    if (warp >= n) return;
    int node = warp;
    int beg = g_rowptr[node];
    int end = g_rowptr[node + 1];

    const float4* self = (const float4*)&g_h[(size_t)node * HH];
    float4 acc[4];
#pragma unroll
    for (int i = 0; i < 4; i++) acc[i] = self[lane + i * 32];

    for (int e = beg; e < end; e++) {
        int r = g_srcidx[e];
        const float4* src = (const float4*)&g_h[(size_t)r * HH];
#pragma unroll
        for (int i = 0; i < 4; i++) {
            float4 v = src[lane + i * 32];
            acc[i].x += v.x; acc[i].y += v.y; acc[i].z += v.z; acc[i].w += v.w;
        }
    }

    float s = g_dinv[node];
    float* dst = &out[(size_t)node * HH];
#pragma unroll
    for (int i = 0; i < 4; i++) {
        int c4 = lane + i * 32;
        float4 bb = *(const float4*)&b[c4 * 4];
        float4 aa = *(const float4*)&alpha[c4 * 4];
        float4 v = acc[i];
        v.x = v.x * s + bb.x;  v.x = v.x > 0.f ? v.x : aa.x * v.x;
        v.y = v.y * s + bb.y;  v.y = v.y > 0.f ? v.y : aa.y * v.y;
        v.z = v.z * s + bb.z;  v.z = v.z > 0.f ? v.z : aa.z * v.z;
        v.w = v.w * s + bb.w;  v.w = v.w > 0.f ? v.w : aa.w * v.w;
        *(float4*)&dst[c4 * 4] = v;
    }
}

// ---------------------------------------------------------------------------
// Launch
// ---------------------------------------------------------------------------
extern "C" void kernel_launch(void* const* d_in, const int* in_sizes, int n_in,
                              void* d_out, int out_size) {
    const float* x     = (const float*)d_in[0];  // [N, 128]
    const int*   ei    = (const int*)d_in[1];    // [2, E] int32
    const float* W     = (const float*)d_in[2];  // [512, 128]
    const float* b     = (const float*)d_in[3];  // [512]
    const float* alpha = (const float*)d_in[4];  // [512]
    float*       out   = (float*)d_out;          // [N, 512]

    const int N = in_sizes[0] / FF;
    const int E = in_sizes[1] / 2;
    const int nb = (N + SCAN_B - 1) / SCAN_B;

    // 1) CSR build (by target) + dinv
    zero_cnt_kernel<<<(N + 255) / 256, 256>>>(N);
    count_kernel<<<(E + 255) / 256, 256>>>(ei, E, N);
    dinv_kernel<<<(N + 255) / 256, 256>>>(N);
    scan_block_kernel<<<nb, SCAN_B>>>(N);
    scan_sums_kernel<<<1, 256>>>(nb);
    add_off_kernel<<<(N + 255) / 256, 256>>>(N, E);
    fill_kernel<<<(E + 255) / 256, 256>>>(ei, E, N);

    // 2) g_h = (x @ W^T) * dinv[row]  — tf32 tensor cores
    dim3 gemm_grid(HH / 128, (N + 127) / 128);
    tf32_gemm_kernel<<<gemm_grid, 256>>>(x, W, N);

    // 3) pull-based aggregate + finalize (warp per node)
    int warps_per_block = 256 / 32;
    pull_kernel<<<(N + warps_per_block - 1) / warps_per_block, 256>>>(out, b, alpha, N);
}

// round 7
// speedup vs baseline: 4.2061x; 1.2213x over previous
#include <cuda_runtime.h>
#include <cstdint>

#define FF 128
#define HH 512
#define MAXN 50048
#define MAXE 401408
#define SCAN_B 1024

// Scratch (static device globals — no runtime allocation allowed)
__device__ float g_h[(size_t)50000 * HH];   // h' = (x @ W^T) * dinv[row]
__device__ int   g_cnt[MAXN];
__device__ float g_dinv[MAXN];
__device__ int   g_rowptr[MAXN + 1];
__device__ int   g_cur[MAXN];
__device__ int   g_srcidx[MAXE];
__device__ int   g_bsum[256];
__device__ int   g_boff[256];

// ---------------------------------------------------------------------------
// CSR build: count -> scan -> fill
// ---------------------------------------------------------------------------
__global__ void zero_cnt_kernel(int n) {
    int i = blockIdx.x * blockDim.x + threadIdx.x;
    if (i < n) g_cnt[i] = 0;
}

__global__ void count_kernel(const int* __restrict__ ei, int E, int n) {
    int e = blockIdx.x * blockDim.x + threadIdx.x;
    if (e < E) {
        int c = ei[E + e];
        if ((unsigned)c < (unsigned)n) atomicAdd(&g_cnt[c], 1);
    }
}

__global__ void dinv_kernel(int n) {
    int i = blockIdx.x * blockDim.x + threadIdx.x;
    if (i < n) g_dinv[i] = rsqrtf((float)(g_cnt[i] + 1));  // +1 self-loop
}

__global__ void scan_block_kernel(int n) {
    __shared__ int sh[SCAN_B];
    int gid = blockIdx.x * SCAN_B + threadIdx.x;
    int v = (gid < n) ? g_cnt[gid] : 0;
    sh[threadIdx.x] = v;
    __syncthreads();
#pragma unroll
    for (int off = 1; off < SCAN_B; off <<= 1) {
        int t = (threadIdx.x >= off) ? sh[threadIdx.x - off] : 0;
        __syncthreads();
        sh[threadIdx.x] += t;
        __syncthreads();
    }
    if (gid < n) g_rowptr[gid] = sh[threadIdx.x] - v;   // exclusive
    if (threadIdx.x == SCAN_B - 1) g_bsum[blockIdx.x] = sh[threadIdx.x];
}

__global__ void scan_sums_kernel(int nb) {
    __shared__ int sh[256];
    int v = (threadIdx.x < nb) ? g_bsum[threadIdx.x] : 0;
    sh[threadIdx.x] = v;
    __syncthreads();
#pragma unroll
    for (int off = 1; off < 256; off <<= 1) {
        int t = (threadIdx.x >= off) ? sh[threadIdx.x - off] : 0;
        __syncthreads();
        sh[threadIdx.x] += t;
        __syncthreads();
    }
    if (threadIdx.x < nb) g_boff[threadIdx.x] = sh[threadIdx.x] - v;  // exclusive
}

__global__ void add_off_kernel(int n, int E) {
    int i = blockIdx.x * blockDim.x + threadIdx.x;
    if (i < n) {
        int v = g_rowptr[i] + g_boff[i / SCAN_B];
        g_rowptr[i] = v;
        g_cur[i] = v;
    }
    if (i == 0) g_rowptr[n] = E;
}

__global__ void fill_kernel(const int* __restrict__ ei, int E, int n) {
    int e = blockIdx.x * blockDim.x + threadIdx.x;
    if (e < E) {
        int r = ei[e];
        int c = ei[E + e];
        if ((unsigned)r < (unsigned)n && (unsigned)c < (unsigned)n) {
            int pos = atomicAdd(&g_cur[c], 1);
            g_srcidx[pos] = r;
        }
    }
}

// ---------------------------------------------------------------------------
// tf32 tensor-core GEMM, A-resident + cp.async double-buffered B.
// One block computes 128 rows x all 512 cols.
//   smem: As[128][132] tf32 (full K), Bs[2][128][36] fp32 (one 32-k tile, 2 buf)
// ---------------------------------------------------------------------------
#define AS_LD 132
#define BS_LD 36
#define AS_BYTES (128 * AS_LD * 4)            // 67584
#define BS_BYTES (2 * 128 * BS_LD * 4)        // 36864
#define SMEM_TOTAL_GEMM (AS_BYTES + BS_BYTES) // 104448

__device__ __forceinline__ uint32_t f2tf(float x) {
    uint32_t u;
    asm("cvt.rna.tf32.f32 %0, %1;" : "=r"(u) : "f"(x));
    return u;
}

__device__ __forceinline__ void mma8(float* c, const uint32_t* a,
                                     uint32_t b0, uint32_t b1) {
    asm volatile(
        "mma.sync.aligned.m16n8k8.row.col.f32.tf32.tf32.f32 "
        "{%0,%1,%2,%3}, {%4,%5,%6,%7}, {%8,%9}, {%0,%1,%2,%3};"
        : "+f"(c[0]), "+f"(c[1]), "+f"(c[2]), "+f"(c[3])
        : "r"(a[0]), "r"(a[1]), "r"(a[2]), "r"(a[3]), "r"(b0), "r"(b1));
}

__device__ __forceinline__ void cp_async16(void* sptr, const void* gptr) {
    uint32_t sa = (uint32_t)__cvta_generic_to_shared(sptr);
    asm volatile("cp.async.cg.shared.global [%0], [%1], 16;" :: "r"(sa), "l"(gptr));
}
__device__ __forceinline__ void cp_commit() {
    asm volatile("cp.async.commit_group;");
}
template <int NN>
__device__ __forceinline__ void cp_wait() {
    asm volatile("cp.async.wait_group %0;" :: "n"(NN));
}

__global__ __launch_bounds__(256) void tf32_gemm_kernel(
        const float* __restrict__ X, const float* __restrict__ W, int M) {
    extern __shared__ char smem_raw[];
    uint32_t (*As)[AS_LD]       = (uint32_t(*)[AS_LD])smem_raw;
    float    (*Bs)[128][BS_LD]  = (float(*)[128][BS_LD])(smem_raw + AS_BYTES);

    const int t    = threadIdx.x;
    const int wid  = t >> 5;
    const int lane = t & 31;
    const int warp_m = wid & 3;   // 4 warps along M (32 rows each)
    const int warp_n = wid >> 2;  // 2 warps along N-subtile (64 cols each)
    const int bm = blockIdx.x * 128;

    // ---- load full A tile (128 rows x 128 k), convert to tf32 ----
#pragma unroll
    for (int i = 0; i < 16; i++) {
        int idx = t + i * 256;          // 0..4095
        int row = idx >> 5;             // 0..127
        int c4  = idx & 31;             // 0..31
        int gm  = bm + row;
        float4 v = make_float4(0.f, 0.f, 0.f, 0.f);
        if (gm < M) v = *(const float4*)&X[(size_t)gm * FF + c4 * 4];
        uint32_t* s = &As[row][c4 * 4];
        s[0] = f2tf(v.x); s[1] = f2tf(v.y); s[2] = f2tf(v.z); s[3] = f2tf(v.w);
    }

    // B tile loader: tile s -> (nt = s>>2 N-block of 128 cols, kt = s&3 k-block)
    auto issueB = [&](int s, int buf) {
        int nt = s >> 2, kt = s & 3;
#pragma unroll
        for (int i = 0; i < 4; i++) {
            int idx = t + i * 256;      // 0..1023
            int row = idx >> 3;         // 0..127 (W row within nt block)
            int c4  = idx & 7;          // 0..7
            cp_async16(&Bs[buf][row][c4 * 4],
                       &W[(size_t)(nt * 128 + row) * FF + kt * 32 + c4 * 4]);
        }
        cp_commit();
    };

    issueB(0, 0);
    __syncthreads();   // As visible to all (cp.async ordering handled by wait)

    float c[2][8][4];
#pragma unroll
    for (int mt = 0; mt < 2; mt++)
#pragma unroll
        for (int j = 0; j < 8; j++)
#pragma unroll
            for (int q = 0; q < 4; q++) c[mt][j][q] = 0.f;

    const int fr = lane >> 2;      // 0..7
    const int fc = lane & 3;       // 0..3

    for (int s = 0; s < 16; s++) {
        int buf = s & 1;
        if (s < 15) { issueB(s + 1, buf ^ 1); cp_wait<1>(); }
        else        { cp_wait<0>(); }
        __syncthreads();

        const int kt = s & 3;
#pragma unroll
        for (int ks = 0; ks < 4; ks++) {
            const int kcA = kt * 32 + ks * 8 + fc;   // column in As
            const int kcB = ks * 8 + fc;             // column in Bs tile
            uint32_t a[2][4];
#pragma unroll
            for (int mt = 0; mt < 2; mt++) {
                int r = warp_m * 32 + mt * 16 + fr;
                a[mt][0] = As[r][kcA];
                a[mt][1] = As[r + 8][kcA];
                a[mt][2] = As[r][kcA + 4];
                a[mt][3] = As[r + 8][kcA + 4];
            }
#pragma unroll
            for (int j = 0; j < 8; j++) {
                int nr = warp_n * 64 + j * 8 + fr;
                uint32_t b0 = f2tf(Bs[buf][nr][kcB]);
                uint32_t b1 = f2tf(Bs[buf][nr][kcB + 4]);
#pragma unroll
                for (int mt = 0; mt < 2; mt++)
                    mma8(c[mt][j], a[mt], b0, b1);
            }
        }
        __syncthreads();   // everyone done reading Bs[buf] before it is refilled

        if ((s & 3) == 3) {
            // end of this N-block: scale by dinv[row], store, reset accum
            int nt = s >> 2;
#pragma unroll
            for (int mt = 0; mt < 2; mt++) {
                int r0 = bm + warp_m * 32 + mt * 16 + fr;
                int r1 = r0 + 8;
                float s0 = (r0 < M) ? g_dinv[r0] : 0.f;
                float s1 = (r1 < M) ? g_dinv[r1] : 0.f;
#pragma unroll
                for (int j = 0; j < 8; j++) {
                    int col = nt * 128 + warp_n * 64 + j * 8 + fc * 2;
                    if (r0 < M) {
                        float2 v = make_float2(c[mt][j][0] * s0, c[mt][j][1] * s0);
                        *(float2*)&g_h[(size_t)r0 * HH + col] = v;
                    }
                    if (r1 < M) {
                        float2 v = make_float2(c[mt][j][2] * s1, c[mt][j][3] * s1);
                        *(float2*)&g_h[(size_t)r1 * HH + col] = v;
                    }
#pragma unroll
                    for (int q = 0; q < 4; q++) c[mt][j][q] = 0.f;
                }
            }
        }
    }
}

// ---------------------------------------------------------------------------
// Pull + finalize fused: one warp per node.
// ---------------------------------------------------------------------------
__global__ void pull_kernel(float* __restrict__ out,
                            const float* __restrict__ b,
                            const float* __restrict__ alpha,
                            int n) {
    int warp = (blockIdx.x * blockDim.x + threadIdx.x) >> 5;
    int lane = threadIdx.x & 31;
    if (warp >= n) return;
    int node = warp;
    int beg = g_rowptr[node];
    int end = g_rowptr[node + 1];

    const float4* self = (const float4*)&g_h[(size_t)node * HH];
    float4 acc[4];
#pragma unroll
    for (int i = 0; i < 4; i++) acc[i] = self[lane + i * 32];

    for (int e = beg; e < end; e++) {
        int r = g_srcidx[e];
        const float4* src = (const float4*)&g_h[(size_t)r * HH];
#pragma unroll
        for (int i = 0; i < 4; i++) {
            float4 v = src[lane + i * 32];
            acc[i].x += v.x; acc[i].y += v.y; acc[i].z += v.z; acc[i].w += v.w;
        }
    }

    float s = g_dinv[node];
    float* dst = &out[(size_t)node * HH];
#pragma unroll
    for (int i = 0; i < 4; i++) {
        int c4 = lane + i * 32;
        float4 bb = *(const float4*)&b[c4 * 4];
        float4 aa = *(const float4*)&alpha[c4 * 4];
        float4 v = acc[i];
        v.x = v.x * s + bb.x;  v.x = v.x > 0.f ? v.x : aa.x * v.x;
        v.y = v.y * s + bb.y;  v.y = v.y > 0.f ? v.y : aa.y * v.y;
        v.z = v.z * s + bb.z;  v.z = v.z > 0.f ? v.z : aa.z * v.z;
        v.w = v.w * s + bb.w;  v.w = v.w > 0.f ? v.w : aa.w * v.w;
        *(float4*)&dst[c4 * 4] = v;
    }
}

// ---------------------------------------------------------------------------
// Launch
// ---------------------------------------------------------------------------
extern "C" void kernel_launch(void* const* d_in, const int* in_sizes, int n_in,
                              void* d_out, int out_size) {
    const float* x     = (const float*)d_in[0];  // [N, 128]
    const int*   ei    = (const int*)d_in[1];    // [2, E] int32
    const float* W     = (const float*)d_in[2];  // [512, 128]
    const float* b     = (const float*)d_in[3];  // [512]
    const float* alpha = (const float*)d_in[4];  // [512]
    float*       out   = (float*)d_out;          // [N, 512]

    const int N = in_sizes[0] / FF;
    const int E = in_sizes[1] / 2;
    const int nb = (N + SCAN_B - 1) / SCAN_B;

    cudaFuncSetAttribute(tf32_gemm_kernel,
                         cudaFuncAttributeMaxDynamicSharedMemorySize,
                         SMEM_TOTAL_GEMM);

    // 1) CSR build (by target) + dinv
    zero_cnt_kernel<<<(N + 255) / 256, 256>>>(N);
    count_kernel<<<(E + 255) / 256, 256>>>(ei, E, N);
    dinv_kernel<<<(N + 255) / 256, 256>>>(N);
    scan_block_kernel<<<nb, SCAN_B>>>(N);
    scan_sums_kernel<<<1, 256>>>(nb);
    add_off_kernel<<<(N + 255) / 256, 256>>>(N, E);
    fill_kernel<<<(E + 255) / 256, 256>>>(ei, E, N);

    // 2) g_h = (x @ W^T) * dinv[row]  — tf32 TC, A-resident, async B pipeline
    tf32_gemm_kernel<<<(N + 127) / 128, 256, SMEM_TOTAL_GEMM>>>(x, W, N);

    // 3) pull-based aggregate + finalize (warp per node)
    int warps_per_block = 256 / 32;
    pull_kernel<<<(N + warps_per_block - 1) / warps_per_block, 256>>>(out, b, alpha, N);
}